// round 13
// baseline (speedup 1.0000x reference)
#include <cuda_runtime.h>
#include <cuda_fp16.h>

// Gridding R12: R10 quarter-split 2-RED/point fp16x2 parity scatter
// (1 pt/thread — R11's 4pt variant regressed), plus a two-stream
// fork/join pipeline overlapping combine(q) with scatter(q+1) using
// double-buffered parity scratch.

#define GB 64
#define GBQ 16
#define GN 65536
#define GS 64
#define GRID_CELLS  (GS * GS * GS)
#define QTR_PTS     (GBQ * GN)                  // 1048576
#define PLANE_WORDS 2048
#define GRID_WORDS  ((size_t)GBQ * GS * PLANE_WORDS)  // 2097152 words = 8.4 MB
#define BUF_WORDS   (4 * GRID_WORDS)            // one 4-parity buffer (33.5 MB)

// Two double-buffered 4-parity scratch grids. Zero-initialized at load;
// every combine clears what it reads, so each replay starts from zeros.
__device__ unsigned int g_S[2 * BUF_WORDS];     // 67 MB

// ---------------------------------------------------------------- scatter
__global__ __launch_bounds__(256) void scatter_kernel(const float* __restrict__ pt,
                                                      int buf) {
    int gid = blockIdx.x * blockDim.x + threadIdx.x;
    if (gid >= QTR_PTS) return;

    int b = gid >> 16;                          // local batch 0..15

    const float* p3 = pt + (size_t)gid * 3;
    float px = p3[0] * 32.0f;
    float py = p3[1] * 32.0f;
    float pz = p3[2] * 32.0f;

    if (fabsf(px) + fabsf(py) + fabsf(pz) == 0.0f) return;

    float lx = floorf(px), ly = floorf(py), lz = floorf(pz);
    float fx = px - lx, fy = py - ly, fz = pz - lz;

    int ix = (int)lx + 32;                      // uniform input: [0,63]
    int iy = (int)ly + 32;
    int iz = (int)lz + 32;

    float wy0 = 1.0f - fy, wy1 = fy;
    float wz0 = 1.0f - fz, wz1 = fz;

    float a00 = wy0 * wz0, a01 = wy0 * wz1;
    float a10 = wy1 * wz0, a11 = wy1 * wz1;

    int p = ((iy & 1) << 1) | (iz & 1);
    unsigned int* base = g_S + (size_t)buf * BUF_WORDS + (size_t)p * GRID_WORDS;
    int zw = iz >> 1;
    int ypair = iy & ~1;

    float wx[2] = {1.0f - fx, fx};

    #pragma unroll
    for (int i = 0; i < 2; i++) {
        int X = ix + i;
        if (X >= GS) continue;
        float w = wx[i];
        __half2 h0 = __floats2half2_rn(w * a00, w * a01);
        __half2 h1 = __floats2half2_rn(w * a10, w * a11);
        unsigned int r0 = *(unsigned int*)&h0;
        unsigned int r1 = *(unsigned int*)&h1;
        size_t word = (((size_t)(b * GS + X) * 32 + zw) << 6) + ypair;
        asm volatile("red.global.add.noftz.v2.f16x2 [%0], {%1, %2};"
                     :: "l"(base + word), "r"(r0), "r"(r1) : "memory");
    }
}

// ---------------------------------------------------------------- combine
__device__ __forceinline__ float half_of(unsigned int w, int k) {
    __half2 h = *(__half2*)&w;
    return k ? __high2float(h) : __low2float(h);
}

__global__ __launch_bounds__(256) void combine_kernel(float* __restrict__ out,
                                                      int buf) {
    __shared__ unsigned int s[4][PLANE_WORDS];
    int cta = blockIdx.x;                       // b_local*64 + X
    int t = threadIdx.x;
    size_t pbase = (size_t)cta * PLANE_WORDS;
    unsigned int* S = g_S + (size_t)buf * BUF_WORDS;

    uint4 v[4][2];
    #pragma unroll
    for (int g = 0; g < 4; g++) {
        uint4* gp = (uint4*)(S + (size_t)g * GRID_WORDS + pbase);
        #pragma unroll
        for (int i = 0; i < 2; i++) v[g][i] = gp[t + i * 256];
    }
    #pragma unroll
    for (int g = 0; g < 4; g++) {
        uint4* sp = (uint4*)s[g];
        uint4* gp = (uint4*)(S + (size_t)g * GRID_WORDS + pbase);
        #pragma unroll
        for (int i = 0; i < 2; i++) {
            sp[t + i * 256] = v[g][i];
            gp[t + i * 256] = make_uint4(0u, 0u, 0u, 0u);
        }
    }
    __syncthreads();

    int Y = t >> 2;
    int Z0 = (t & 3) << 4;

    float res[16];
    #pragma unroll
    for (int i = 0; i < 16; i++) {
        int Z = Z0 + i;
        float r = half_of(s[0][(Z >> 1) * 64 + Y], Z & 1);
        if (Z > 0)
            r += half_of(s[1][((Z - 1) >> 1) * 64 + Y], (Z - 1) & 1);
        if (Y > 0) {
            r += half_of(s[2][(Z >> 1) * 64 + (Y - 1)], Z & 1);
            if (Z > 0)
                r += half_of(s[3][((Z - 1) >> 1) * 64 + (Y - 1)], (Z - 1) & 1);
        }
        res[i] = r;
    }

    float4* o = (float4*)(out + ((size_t)cta * 64 + Y) * 64 + Z0);
    o[0] = make_float4(res[0],  res[1],  res[2],  res[3]);
    o[1] = make_float4(res[4],  res[5],  res[6],  res[7]);
    o[2] = make_float4(res[8],  res[9],  res[10], res[11]);
    o[3] = make_float4(res[12], res[13], res[14], res[15]);
}

extern "C" void kernel_launch(void* const* d_in, const int* in_sizes, int n_in,
                              void* d_out, int out_size) {
    const float* pt = (const float*)d_in[0];
    float* out = (float*)d_out;

    // Lazily created host-side resources (no device memory involved).
    static cudaStream_t s2 = nullptr;
    static cudaEvent_t e_sc[4], e_cb[4];
    if (s2 == nullptr) {
        cudaStreamCreateWithFlags(&s2, cudaStreamNonBlocking);
        for (int i = 0; i < 4; i++) {
            cudaEventCreateWithFlags(&e_sc[i], cudaEventDisableTiming);
            cudaEventCreateWithFlags(&e_cb[i], cudaEventDisableTiming);
        }
    }

    int threads = 256;
    int sblocks = (QTR_PTS + threads - 1) / threads;

    for (int q = 0; q < 4; q++) {
        int buf = q & 1;
        const float* ptq = pt + (size_t)q * GBQ * GN * 3;
        float* outq = out + (size_t)q * GBQ * GRID_CELLS;

        // Buffer reuse: scatter q needs combine (q-2) to have cleared it.
        if (q >= 2) cudaStreamWaitEvent(0, e_cb[q - 2], 0);
        scatter_kernel<<<sblocks, threads>>>(ptq, buf);
        cudaEventRecord(e_sc[q], 0);

        // Combine on side stream, after its scatter.
        cudaStreamWaitEvent(s2, e_sc[q], 0);
        combine_kernel<<<GBQ * GS, 256, 0, s2>>>(outq, buf);
        cudaEventRecord(e_cb[q], s2);
    }
    // Join side stream back into the main (captured) stream.
    cudaStreamWaitEvent(0, e_cb[3], 0);
}